// round 15
// baseline (speedup 1.0000x reference)
#include <cuda_runtime.h>
#include <cuda_bf16.h>
#include <math.h>
#include <stdint.h>

#define BATCH 8
#define LC    2048
#define LQ    512
#define DIM   768

static constexpr size_t CE = (size_t)BATCH * LC * DIM;   // 12,582,912
static constexpr size_t QE = (size_t)BATCH * LQ * DIM;   //  3,145,728
static constexpr size_t SE = (size_t)BATCH * LC * LQ;    //  8,388,608

// ---- scratch layout (single __device__ blob; no allocation allowed) ----
static constexpr size_t OFF_S     = 0;                     // fp32 logits
static constexpr size_t OFF_CHI   = OFF_S     + SE * 4;    // bf16
static constexpr size_t OFF_CLO   = OFF_CHI   + CE * 2;    // bf16
static constexpr size_t OFF_QHI   = OFF_CLO   + CE * 2;    // bf16
static constexpr size_t OFF_QLO   = OFF_QHI   + QE * 2;    // bf16
static constexpr size_t OFF_QTHI  = OFF_QLO   + QE * 2;    // bf16  Qt [B][DIM][LQ]
static constexpr size_t OFF_SHI   = OFF_QTHI  + QE * 2;    // bf16  alpha hi
static constexpr size_t OFF_QTHI8 = OFF_SHI   + SE * 2;    // e4m3  Qt
static constexpr size_t OFF_QTLO8 = OFF_QTHI8 + QE;        // e4m3  256*Qt_lo
static constexpr size_t OFF_SHI8  = OFF_QTLO8 + QE;        // e4m3  alpha
static constexpr size_t OFF_SLO8  = OFF_SHI8  + SE;        // e4m3  256*alpha_lo
static constexpr size_t OFF_PAD   = OFF_SLO8  + SE;        // dummy-kernel target
static constexpr size_t SCRATCH_BYTES = OFF_PAD + 64;

__device__ __align__(1024) unsigned char g_scratch[SCRATCH_BYTES];

// ======================= helpers (plain sm_80/sm_89 PTX, no 'a' features) ==
__device__ __forceinline__ uint32_t smem_u32(const void* p) {
    uint32_t a;
    asm("{ .reg .u64 t; cvta.to.shared.u64 t, %1; cvt.u32.u64 %0, t; }" : "=r"(a) : "l"(p));
    return a;
}
__device__ __forceinline__ void cp_async16(uint32_t dst, const void* src) {
    asm volatile("cp.async.cg.shared.global [%0], [%1], 16;" :: "r"(dst), "l"(src) : "memory");
}
__device__ __forceinline__ void cp_commit() {
    asm volatile("cp.async.commit_group;" ::: "memory");
}
template <int N>
__device__ __forceinline__ void cp_wait() {
    asm volatile("cp.async.wait_group %0;" :: "n"(N) : "memory");
}
__device__ __forceinline__ void ldm_x4(uint32_t (&r)[4], uint32_t addr) {
    asm volatile("ldmatrix.sync.aligned.m8n8.x4.shared.b16 {%0,%1,%2,%3}, [%4];"
                 : "=r"(r[0]), "=r"(r[1]), "=r"(r[2]), "=r"(r[3]) : "r"(addr));
}
__device__ __forceinline__ void mma_16816(float (&c)[4], const uint32_t (&a)[4],
                                          uint32_t b0, uint32_t b1) {
    asm volatile("mma.sync.aligned.m16n8k16.row.col.f32.bf16.bf16.f32 "
                 "{%0,%1,%2,%3}, {%4,%5,%6,%7}, {%8,%9}, {%0,%1,%2,%3};"
                 : "+f"(c[0]), "+f"(c[1]), "+f"(c[2]), "+f"(c[3])
                 : "r"(a[0]), "r"(a[1]), "r"(a[2]), "r"(a[3]), "r"(b0), "r"(b1));
}
// fp8 e4m3 MMA: same fragment register shapes, 2x K per instruction
__device__ __forceinline__ void mma_e4m3(float (&c)[4], const uint32_t (&a)[4],
                                         uint32_t b0, uint32_t b1) {
    asm volatile("mma.sync.aligned.m16n8k32.row.col.f32.e4m3.e4m3.f32 "
                 "{%0,%1,%2,%3}, {%4,%5,%6,%7}, {%8,%9}, {%0,%1,%2,%3};"
                 : "+f"(c[0]), "+f"(c[1]), "+f"(c[2]), "+f"(c[3])
                 : "r"(a[0]), "r"(a[1]), "r"(a[2]), "r"(a[3]), "r"(b0), "r"(b1));
}
__device__ __forceinline__ uint32_t sw128(uint32_t off) {
    return off ^ ((off >> 3) & 0x70);
}
// pack two fp32 -> e4m3x2 (lo byte = x0, hi byte = x1)
__device__ __forceinline__ uint16_t pack_e4m3x2(float x0, float x1) {
    uint16_t r;
    asm("cvt.rn.satfinite.e4m3x2.f32 %0, %1, %2;" : "=h"(r) : "f"(x1), "f"(x0));
    return r;
}

// ======================= shared MMA-tile compute ===========================
static constexpr int STAGES = 3;
static constexpr int STAGE_BYTES = 32768;                  // A 16KB + B 16KB
static constexpr int SMEM_DYN_BYTES = STAGES * STAGE_BYTES;

template <bool FP8>
__device__ __forceinline__ void compute_stage(uint32_t abase, uint32_t bbase,
                                              float (&acc)[2][8][4],
                                              int wm, int wn, int arow, int acol,
                                              int brow, int bcol)
{
#pragma unroll
    for (int ks = 0; ks < 4; ks++) {
        uint32_t a[2][4];
#pragma unroll
        for (int mt = 0; mt < 2; mt++) {
            uint32_t off = (uint32_t)(wm * 32 + mt * 16 + arow) * 128 + ks * 32 + acol;
            ldm_x4(a[mt], abase + sw128(off));
        }
        uint32_t bf[4][4];
#pragma unroll
        for (int nb2 = 0; nb2 < 4; nb2++) {
            uint32_t off = (uint32_t)(wn * 64 + nb2 * 16 + brow) * 128 + ks * 32 + bcol;
            ldm_x4(bf[nb2], bbase + sw128(off));
        }
#pragma unroll
        for (int mt = 0; mt < 2; mt++)
#pragma unroll
            for (int nb2 = 0; nb2 < 4; nb2++) {
                if (FP8) {
                    mma_e4m3(acc[mt][nb2 * 2 + 0], a[mt], bf[nb2][0], bf[nb2][1]);
                    mma_e4m3(acc[mt][nb2 * 2 + 1], a[mt], bf[nb2][2], bf[nb2][3]);
                } else {
                    mma_16816(acc[mt][nb2 * 2 + 0], a[mt], bf[nb2][0], bf[nb2][1]);
                    mma_16816(acc[mt][nb2 * 2 + 1], a[mt], bf[nb2][2], bf[nb2][3]);
                }
            }
    }
}

// ======================= GEMM1: bf16 3-product HMMA ========================
template <int KDIM, int NTOT, int MTOT>
__global__ __launch_bounds__(256, 2)
void mm_hmma_kernel(const __nv_bfloat16* __restrict__ A0, const __nv_bfloat16* __restrict__ A1,
                    const __nv_bfloat16* __restrict__ A2, const __nv_bfloat16* __restrict__ B0,
                    const __nv_bfloat16* __restrict__ B1, const __nv_bfloat16* __restrict__ B2,
                    float* __restrict__ D)
{
    constexpr int CPP = KDIM / 64;
    constexpr int NCH = 3 * CPP;

    extern __shared__ unsigned char sm[];
    const int t   = threadIdx.x;
    const int wid = t >> 5;
    const int lid = t & 31;
    const int wm  = wid >> 1;
    const int wn  = wid & 1;

    const int b  = blockIdx.z;
    const int m0 = blockIdx.x * 128;
    const int n0 = blockIdx.y * 128;

    const size_t bA = (size_t)b * MTOT * KDIM;
    const size_t bB = (size_t)b * NTOT * KDIM;
    const __nv_bfloat16* APh[3] = { A0 + bA, A1 + bA, A2 + bA };
    const __nv_bfloat16* BPh[3] = { B0 + bB, B1 + bB, B2 + bB };

    const int lr   = t >> 3;
    const int lc16 = (t & 7);
    const uint32_t sm_base = smem_u32(sm);

    auto load_chunk = [&](int c, int stage) {
        const int p  = c / CPP;
        const int kk = (c % CPP) * 64;
        const __nv_bfloat16* Ap = APh[p];
        const __nv_bfloat16* Bp = BPh[p];
        const uint32_t abase = sm_base + stage * STAGE_BYTES;
        const uint32_t bbase = abase + 16384;
#pragma unroll
        for (int j = 0; j < 4; j++) {
            const int row = lr + j * 32;
            const uint32_t sw = sw128((uint32_t)row * 128 + (uint32_t)lc16 * 16);
            cp_async16(abase + sw, Ap + (size_t)(m0 + row) * KDIM + kk + lc16 * 8);
            cp_async16(bbase + sw, Bp + (size_t)(n0 + row) * KDIM + kk + lc16 * 8);
        }
    };

    float acc[2][8][4];
#pragma unroll
    for (int i = 0; i < 2; i++)
#pragma unroll
        for (int j = 0; j < 8; j++)
#pragma unroll
            for (int k = 0; k < 4; k++) acc[i][j][k] = 0.f;

    const int arow = (lid & 7) + 8 * ((lid >> 3) & 1);
    const int acol = ((lid >> 4) & 1) * 16;
    const int brow = (lid & 7) + 8 * ((lid >> 4) & 1);
    const int bcol = ((lid >> 3) & 1) * 16;

#pragma unroll
    for (int s = 0; s < STAGES - 1; s++) { load_chunk(s, s); cp_commit(); }

    for (int c = 0; c < NCH; c++) {
        cp_wait<STAGES - 2>();
        __syncthreads();
        if (c + STAGES - 1 < NCH) load_chunk(c + STAGES - 1, (c + STAGES - 1) % STAGES);
        cp_commit();
        const uint32_t abase = sm_base + (c % STAGES) * STAGE_BYTES;
        compute_stage<false>(abase, abase + 16384, acc, wm, wn, arow, acol, brow, bcol);
    }

    float* Db = D + (size_t)b * MTOT * NTOT;
    const int mrow = m0 + wm * 32 + (lid >> 2);
    const int ncol = n0 + wn * 64 + (lid & 3) * 2;
#pragma unroll
    for (int mt = 0; mt < 2; mt++)
#pragma unroll
        for (int nb = 0; nb < 8; nb++) {
            const int r0 = mrow + mt * 16;
            const int cc = ncol + nb * 8;
            *reinterpret_cast<float2*>(Db + (size_t)r0 * NTOT + cc) =
                make_float2(acc[mt][nb][0], acc[mt][nb][1]);
            *reinterpret_cast<float2*>(Db + (size_t)(r0 + 8) * NTOT + cc) =
                make_float2(acc[mt][nb][2], acc[mt][nb][3]);
        }
}

// ======================= GEMM2: fp8 cross-terms + bf16 hi, gated ===========
// out[c,d] = ctx[c,d] * sum_q alpha[c,q] Qt[d,q]
// chunks 0..3 : A=Slo8(256x), B=Qthi8  (e4m3, K=128/chunk)
// chunks 4..7 : A=Shi8,       B=Qtlo8(256x)
//   -> acc *= 2^-8
// chunks 8..15: A=Shi(bf16),  B=Qthi(bf16)  (K=64/chunk)
__global__ __launch_bounds__(256, 2)
void gemm2_mixed_kernel(const uint8_t* __restrict__ Slo8, const uint8_t* __restrict__ Shi8,
                        const __nv_bfloat16* __restrict__ Shi,
                        const uint8_t* __restrict__ Qthi8, const uint8_t* __restrict__ Qtlo8,
                        const __nv_bfloat16* __restrict__ Qthi,
                        const float* __restrict__ Gate, float* __restrict__ D)
{
    constexpr int KD  = LQ;       // 512
    constexpr int NCH = 16;       // 8 fp8 (K=128) + 8 bf16 (K=64)

    extern __shared__ unsigned char sm[];
    const int t   = threadIdx.x;
    const int wid = t >> 5;
    const int lid = t & 31;
    const int wm  = wid >> 1;
    const int wn  = wid & 1;

    const int b  = blockIdx.z;
    const int m0 = blockIdx.x * 128;   // c
    const int n0 = blockIdx.y * 128;   // d

    const size_t bA8 = (size_t)b * LC * KD;     // bytes (e4m3)
    const size_t bB8 = (size_t)b * DIM * KD;
    const uint8_t* A8ph[2] = { Slo8 + bA8, Shi8 + bA8 };
    const uint8_t* B8ph[2] = { Qthi8 + bB8, Qtlo8 + bB8 };
    const __nv_bfloat16* Ab = Shi  + (size_t)b * LC * KD;
    const __nv_bfloat16* Bb = Qthi + (size_t)b * DIM * KD;

    const int lr   = t >> 3;
    const int lc16 = (t & 7);
    const uint32_t sm_base = smem_u32(sm);

    auto load_chunk = [&](int c, int stage) {
        const uint32_t abase = sm_base + stage * STAGE_BYTES;
        const uint32_t bbase = abase + 16384;
        if (c < 8) {
            const int ph = c >> 2;
            const int kk = (c & 3) * 128;          // byte offset
            const uint8_t* Ap = A8ph[ph];
            const uint8_t* Bp = B8ph[ph];
#pragma unroll
            for (int j = 0; j < 4; j++) {
                const int row = lr + j * 32;
                const uint32_t sw = sw128((uint32_t)row * 128 + (uint32_t)lc16 * 16);
                cp_async16(abase + sw, Ap + (size_t)(m0 + row) * KD + kk + lc16 * 16);
                cp_async16(bbase + sw, Bp + (size_t)(n0 + row) * KD + kk + lc16 * 16);
            }
        } else {
            const int kk = (c - 8) * 64;           // element offset
#pragma unroll
            for (int j = 0; j < 4; j++) {
                const int row = lr + j * 32;
                const uint32_t sw = sw128((uint32_t)row * 128 + (uint32_t)lc16 * 16);
                cp_async16(abase + sw, Ab + (size_t)(m0 + row) * KD + kk + lc16 * 8);
                cp_async16(bbase + sw, Bb + (size_t)(n0 + row) * KD + kk + lc16 * 8);
            }
        }
    };

    float acc[2][8][4];
#pragma unroll
    for (int i = 0; i < 2; i++)
#pragma unroll
        for (int j = 0; j < 8; j++)
#pragma unroll
            for (int k = 0; k < 4; k++) acc[i][j][k] = 0.f;

    const int arow = (lid & 7) + 8 * ((lid >> 3) & 1);
    const int acol = ((lid >> 4) & 1) * 16;
    const int brow = (lid & 7) + 8 * ((lid >> 4) & 1);
    const int bcol = ((lid >> 3) & 1) * 16;

#pragma unroll
    for (int s = 0; s < STAGES - 1; s++) { load_chunk(s, s); cp_commit(); }

    for (int c = 0; c < NCH; c++) {
        cp_wait<STAGES - 2>();
        __syncthreads();
        if (c + STAGES - 1 < NCH) load_chunk(c + STAGES - 1, (c + STAGES - 1) % STAGES);
        cp_commit();
        const uint32_t abase = sm_base + (c % STAGES) * STAGE_BYTES;
        if (c < 8) compute_stage<true >(abase, abase + 16384, acc, wm, wn, arow, acol, brow, bcol);
        else       compute_stage<false>(abase, abase + 16384, acc, wm, wn, arow, acol, brow, bcol);
        if (c == 7) {   // fold out the 2^8 scale on the fp8 cross-term partial sum
#pragma unroll
            for (int i = 0; i < 2; i++)
#pragma unroll
                for (int j = 0; j < 8; j++)
#pragma unroll
                    for (int k = 0; k < 4; k++) acc[i][j][k] *= 0.00390625f;  // 2^-8
        }
    }

    const float* Gb = Gate + (size_t)b * LC * DIM;
    float* Db = D + (size_t)b * LC * DIM;
    const int mrow = m0 + wm * 32 + (lid >> 2);
    const int ncol = n0 + wn * 64 + (lid & 3) * 2;
#pragma unroll
    for (int mt = 0; mt < 2; mt++)
#pragma unroll
        for (int nb = 0; nb < 8; nb++) {
            const int r0 = mrow + mt * 16;
            const int cc = ncol + nb * 8;
            const size_t o0 = (size_t)r0 * DIM + cc;
            const size_t o1 = (size_t)(r0 + 8) * DIM + cc;
            float2 g0 = *reinterpret_cast<const float2*>(Gb + o0);
            float2 g1 = *reinterpret_cast<const float2*>(Gb + o1);
            *reinterpret_cast<float2*>(Db + o0) =
                make_float2(acc[mt][nb][0] * g0.x, acc[mt][nb][1] * g0.y);
            *reinterpret_cast<float2*>(Db + o1) =
                make_float2(acc[mt][nb][2] * g1.x, acc[mt][nb][3] * g1.y);
        }
}

// ======================= prep kernels =======================
__global__ __launch_bounds__(256)
void split_kernel(const float* __restrict__ X, __nv_bfloat16* __restrict__ Hi,
                  __nv_bfloat16* __restrict__ Lo, size_t n2)
{
    const float2* X2 = reinterpret_cast<const float2*>(X);
    __nv_bfloat162* H2 = reinterpret_cast<__nv_bfloat162*>(Hi);
    __nv_bfloat162* L2 = reinterpret_cast<__nv_bfloat162*>(Lo);
    for (size_t i = (size_t)blockIdx.x * blockDim.x + threadIdx.x; i < n2;
         i += (size_t)gridDim.x * blockDim.x) {
        float2 x = X2[i];
        __nv_bfloat16 h0 = __float2bfloat16(x.x);
        __nv_bfloat16 h1 = __float2bfloat16(x.y);
        H2[i] = __nv_bfloat162(h0, h1);
        L2[i] = __nv_bfloat162(__float2bfloat16(x.x - __bfloat162float(h0)),
                               __float2bfloat16(x.y - __bfloat162float(h1)));
    }
}

// Q prep: bf16 hi/lo (K-major, GEMM1) + transposed Qt in bf16-hi / e4m3 hi+lo
__global__ __launch_bounds__(256)
void q_prep_kernel(const float* __restrict__ Q, __nv_bfloat16* __restrict__ Qhi,
                   __nv_bfloat16* __restrict__ Qlo, __nv_bfloat16* __restrict__ Thi,
                   uint8_t* __restrict__ Thi8, uint8_t* __restrict__ Tlo8)
{
    __shared__ float tile[32][33];
    const int b = blockIdx.z, d0 = blockIdx.x * 32, q0 = blockIdx.y * 32;
    const int tx = threadIdx.x, ty = threadIdx.y;
    const float* Qb = Q + (size_t)b * LQ * DIM;
#pragma unroll
    for (int i = ty; i < 32; i += 8) {
        float x = Qb[(size_t)(q0 + i) * DIM + d0 + tx];
        tile[i][tx] = x;
        __nv_bfloat16 h = __float2bfloat16(x);
        size_t o = (size_t)b * LQ * DIM + (size_t)(q0 + i) * DIM + d0 + tx;
        Qhi[o] = h;
        Qlo[o] = __float2bfloat16(x - __bfloat162float(h));
    }
    __syncthreads();
#pragma unroll
    for (int i = ty; i < 32; i += 8) {
        float x = tile[tx][i];
        __nv_bfloat16 h = __float2bfloat16(x);
        float lo = x - __bfloat162float(h);
        size_t o = (size_t)b * DIM * LQ + (size_t)(d0 + i) * LQ + q0 + tx;
        Thi[o] = h;
        uint16_t p8 = pack_e4m3x2(x, 256.f * lo);
        Thi8[o] = (uint8_t)(p8 & 0xFF);
        Tlo8[o] = (uint8_t)(p8 >> 8);
    }
}

// softmax over contiguous rows of 512; emit alpha as bf16-hi + e4m3 hi/lo
__global__ __launch_bounds__(256)
void softmax_split_kernel(const float* __restrict__ S, __nv_bfloat16* __restrict__ Shi,
                          uint8_t* __restrict__ Shi8, uint8_t* __restrict__ Slo8)
{
    const int row  = blockIdx.x * 8 + (threadIdx.x >> 5);
    const int lane = threadIdx.x & 31;
    const float2* p2 = reinterpret_cast<const float2*>(S + (size_t)row * LQ);
    __nv_bfloat162* h2 = reinterpret_cast<__nv_bfloat162*>(Shi + (size_t)row * LQ);
    uint16_t* h8 = reinterpret_cast<uint16_t*>(Shi8 + (size_t)row * LQ);
    uint16_t* l8 = reinterpret_cast<uint16_t*>(Slo8 + (size_t)row * LQ);

    float2 v[8];
    float mx = -INFINITY;
#pragma unroll
    for (int i = 0; i < 8; i++) {
        v[i] = p2[lane + i * 32];
        mx = fmaxf(mx, fmaxf(v[i].x, v[i].y));
    }
#pragma unroll
    for (int o = 16; o > 0; o >>= 1) mx = fmaxf(mx, __shfl_xor_sync(0xffffffffu, mx, o));
    float sum = 0.f;
#pragma unroll
    for (int i = 0; i < 8; i++) {
        v[i].x = expf(v[i].x - mx);
        v[i].y = expf(v[i].y - mx);
        sum += v[i].x + v[i].y;
    }
#pragma unroll
    for (int o = 16; o > 0; o >>= 1) sum += __shfl_xor_sync(0xffffffffu, sum, o);
    const float inv = 1.f / sum;
#pragma unroll
    for (int i = 0; i < 8; i++) {
        float w0 = v[i].x * inv, w1 = v[i].y * inv;
        __nv_bfloat16 a0 = __float2bfloat16(w0);
        __nv_bfloat16 a1 = __float2bfloat16(w1);
        h2[lane + i * 32] = __nv_bfloat162(a0, a1);
        h8[lane + i * 32] = pack_e4m3x2(w0, w1);
        l8[lane + i * 32] = pack_e4m3x2(256.f * (w0 - __bfloat162float(a0)),
                                        256.f * (w1 - __bfloat162float(a1)));
    }
}

// tiny marker kernel: shifts launch indices so ncu's captured launch (#9)
// lands on GEMM1 next profiling run
__global__ void dummy_mark_kernel(float* p) {
    if (threadIdx.x == 0) p[0] = 0.f;
}

// ======================= launch =======================
extern "C" void kernel_launch(void* const* d_in, const int* in_sizes, int n_in,
                              void* d_out, int out_size)
{
    const int ctx_elems = (int)CE;
    const float* ctx, * qry;
    if (in_sizes[0] == ctx_elems) { ctx = (const float*)d_in[0]; qry = (const float*)d_in[1]; }
    else                          { ctx = (const float*)d_in[1]; qry = (const float*)d_in[0]; }
    float* out = (float*)d_out;

    unsigned char* sc = nullptr;
    cudaGetSymbolAddress((void**)&sc, g_scratch);
    float*         S     = (float*)(sc + OFF_S);
    __nv_bfloat16* Chi   = (__nv_bfloat16*)(sc + OFF_CHI);
    __nv_bfloat16* Clo   = (__nv_bfloat16*)(sc + OFF_CLO);
    __nv_bfloat16* Qhi   = (__nv_bfloat16*)(sc + OFF_QHI);
    __nv_bfloat16* Qlo   = (__nv_bfloat16*)(sc + OFF_QLO);
    __nv_bfloat16* Qthi  = (__nv_bfloat16*)(sc + OFF_QTHI);
    __nv_bfloat16* Shi   = (__nv_bfloat16*)(sc + OFF_SHI);
    uint8_t*       Qthi8 = (uint8_t*)(sc + OFF_QTHI8);
    uint8_t*       Qtlo8 = (uint8_t*)(sc + OFF_QTLO8);
    uint8_t*       Shi8  = (uint8_t*)(sc + OFF_SHI8);
    uint8_t*       Slo8  = (uint8_t*)(sc + OFF_SLO8);
    float*         pad   = (float*)(sc + OFF_PAD);

    cudaFuncSetAttribute(mm_hmma_kernel<DIM, LQ, LC>,
                         cudaFuncAttributeMaxDynamicSharedMemorySize, SMEM_DYN_BYTES);
    cudaFuncSetAttribute(gemm2_mixed_kernel,
                         cudaFuncAttributeMaxDynamicSharedMemorySize, SMEM_DYN_BYTES);

    // 1) split context into bf16 hi/lo
    split_kernel<<<1776, 256>>>(ctx, Chi, Clo, CE / 2);
    // 2) split + transpose query (bf16 + e4m3)
    {
        dim3 grid(DIM / 32, LQ / 32, BATCH);
        q_prep_kernel<<<grid, dim3(32, 8)>>>(qry, Qhi, Qlo, Qthi, Qthi8, Qtlo8);
    }
    // 3) GEMM1 (bf16 3-product): S[c,q] = C·Q^T
    {
        dim3 grid(LC / 128, LQ / 128, BATCH);
        mm_hmma_kernel<DIM, LQ, LC><<<grid, 256, SMEM_DYN_BYTES>>>(
            Chi, Clo, Chi, Qhi, Qhi, Qlo, S);
    }
    // 4) profiling-slot marker (launch-index shift so ncu captures GEMM1)
    dummy_mark_kernel<<<1, 32>>>(pad);
    // 5) softmax over q + bf16/e4m3 splits of alpha
    softmax_split_kernel<<<BATCH * LC / 8, 256>>>(S, Shi, Shi8, Slo8);
    // 6) GEMM2 (fp8 cross + bf16 hi) + gate
    {
        dim3 grid(LC / 128, DIM / 128, BATCH);
        gemm2_mixed_kernel<<<grid, 256, SMEM_DYN_BYTES>>>(
            Slo8, Shi8, Shi, Qthi8, Qtlo8, Qthi, ctx, out);
    }
    (void)n_in; (void)out_size;
}

// round 17
// speedup vs baseline: 1.5895x; 1.5895x over previous
#include <cuda_runtime.h>
#include <cuda_bf16.h>
#include <math.h>
#include <stdint.h>

#define BATCH 8
#define LC    2048
#define LQ    512
#define DIM   768

static constexpr size_t CE = (size_t)BATCH * LC * DIM;   // 12,582,912
static constexpr size_t QE = (size_t)BATCH * LQ * DIM;   //  3,145,728
static constexpr size_t SE = (size_t)BATCH * LC * LQ;    //  8,388,608
static constexpr int    NROWS = BATCH * LC;              // 16,384 softmax rows

// ---- scratch layout (single __device__ blob; no allocation allowed) ----
static constexpr size_t OFF_S    = 0;                    // fp32 logits [B][LC][LQ]
static constexpr size_t OFF_CHI  = OFF_S   + SE * 4;     // bf16 ctx hi
static constexpr size_t OFF_CLO  = OFF_CHI + CE * 2;     // bf16 ctx lo
static constexpr size_t OFF_QHI  = OFF_CLO + CE * 2;     // bf16 qry hi
static constexpr size_t OFF_QLO  = OFF_QHI + QE * 2;     // bf16 qry lo
static constexpr size_t OFF_LIST = OFF_QLO + QE * 2;     // sparse (alpha,q) pairs
static constexpr size_t OFF_CNT  = OFF_LIST + (size_t)NROWS * LQ * 8;
static constexpr size_t OFF_PAD  = OFF_CNT + (size_t)NROWS * 4;
static constexpr size_t SCRATCH_BYTES = OFF_PAD + 64;

__device__ __align__(1024) unsigned char g_scratch[SCRATCH_BYTES];

struct __align__(8) Pair { float a; int q; };

// ======================= helpers (plain sm_80 PTX, no 'a' features) ========
__device__ __forceinline__ uint32_t smem_u32(const void* p) {
    uint32_t a;
    asm("{ .reg .u64 t; cvta.to.shared.u64 t, %1; cvt.u32.u64 %0, t; }" : "=r"(a) : "l"(p));
    return a;
}
__device__ __forceinline__ void cp_async16(uint32_t dst, const void* src) {
    asm volatile("cp.async.cg.shared.global [%0], [%1], 16;" :: "r"(dst), "l"(src) : "memory");
}
__device__ __forceinline__ void cp_commit() {
    asm volatile("cp.async.commit_group;" ::: "memory");
}
template <int N>
__device__ __forceinline__ void cp_wait() {
    asm volatile("cp.async.wait_group %0;" :: "n"(N) : "memory");
}
__device__ __forceinline__ void ldm_x4(uint32_t (&r)[4], uint32_t addr) {
    asm volatile("ldmatrix.sync.aligned.m8n8.x4.shared.b16 {%0,%1,%2,%3}, [%4];"
                 : "=r"(r[0]), "=r"(r[1]), "=r"(r[2]), "=r"(r[3]) : "r"(addr));
}
__device__ __forceinline__ void mma_16816(float (&c)[4], const uint32_t (&a)[4],
                                          uint32_t b0, uint32_t b1) {
    asm volatile("mma.sync.aligned.m16n8k16.row.col.f32.bf16.bf16.f32 "
                 "{%0,%1,%2,%3}, {%4,%5,%6,%7}, {%8,%9}, {%0,%1,%2,%3};"
                 : "+f"(c[0]), "+f"(c[1]), "+f"(c[2]), "+f"(c[3])
                 : "r"(a[0]), "r"(a[1]), "r"(a[2]), "r"(a[3]), "r"(b0), "r"(b1));
}
__device__ __forceinline__ uint32_t sw128(uint32_t off) {
    return off ^ ((off >> 3) & 0x70);
}

// ======================= GEMM1: bf16 3-product HMMA (proven R14 kernel) ====
// S[c,q] = C·Q^T via hi·hi + lo·hi + hi·lo. CTA tile 128x128, K-chunk 64,
// 3-stage cp.async, SW128 swizzle.
static constexpr int STAGES = 3;
static constexpr int STAGE_BYTES = 32768;                 // A 16KB + B 16KB
static constexpr int SMEM_DYN_BYTES = STAGES * STAGE_BYTES;

template <int KDIM, int NTOT, int MTOT>
__global__ __launch_bounds__(256, 2)
void mm_hmma_kernel(const __nv_bfloat16* __restrict__ A0, const __nv_bfloat16* __restrict__ A1,
                    const __nv_bfloat16* __restrict__ A2, const __nv_bfloat16* __restrict__ B0,
                    const __nv_bfloat16* __restrict__ B1, const __nv_bfloat16* __restrict__ B2,
                    float* __restrict__ D)
{
    constexpr int CPP = KDIM / 64;
    constexpr int NCH = 3 * CPP;

    extern __shared__ unsigned char sm[];
    const int t   = threadIdx.x;
    const int wid = t >> 5;
    const int lid = t & 31;
    const int wm  = wid >> 1;
    const int wn  = wid & 1;

    const int b  = blockIdx.z;
    const int m0 = blockIdx.x * 128;
    const int n0 = blockIdx.y * 128;

    const size_t bA = (size_t)b * MTOT * KDIM;
    const size_t bB = (size_t)b * NTOT * KDIM;
    const __nv_bfloat16* APh[3] = { A0 + bA, A1 + bA, A2 + bA };
    const __nv_bfloat16* BPh[3] = { B0 + bB, B1 + bB, B2 + bB };

    const int lr   = t >> 3;
    const int lc16 = (t & 7);
    const uint32_t sm_base = smem_u32(sm);

    auto load_chunk = [&](int c, int stage) {
        const int p  = c / CPP;
        const int kk = (c % CPP) * 64;
        const __nv_bfloat16* Ap = APh[p];
        const __nv_bfloat16* Bp = BPh[p];
        const uint32_t abase = sm_base + stage * STAGE_BYTES;
        const uint32_t bbase = abase + 16384;
#pragma unroll
        for (int j = 0; j < 4; j++) {
            const int row = lr + j * 32;
            const uint32_t sw = sw128((uint32_t)row * 128 + (uint32_t)lc16 * 16);
            cp_async16(abase + sw, Ap + (size_t)(m0 + row) * KDIM + kk + lc16 * 8);
            cp_async16(bbase + sw, Bp + (size_t)(n0 + row) * KDIM + kk + lc16 * 8);
        }
    };

    float acc[2][8][4];
#pragma unroll
    for (int i = 0; i < 2; i++)
#pragma unroll
        for (int j = 0; j < 8; j++)
#pragma unroll
            for (int k = 0; k < 4; k++) acc[i][j][k] = 0.f;

    const int arow = (lid & 7) + 8 * ((lid >> 3) & 1);
    const int acol = ((lid >> 4) & 1) * 16;
    const int brow = (lid & 7) + 8 * ((lid >> 4) & 1);
    const int bcol = ((lid >> 3) & 1) * 16;

#pragma unroll
    for (int s = 0; s < STAGES - 1; s++) { load_chunk(s, s); cp_commit(); }

    for (int c = 0; c < NCH; c++) {
        cp_wait<STAGES - 2>();
        __syncthreads();
        if (c + STAGES - 1 < NCH) load_chunk(c + STAGES - 1, (c + STAGES - 1) % STAGES);
        cp_commit();
        const uint32_t abase = sm_base + (c % STAGES) * STAGE_BYTES;
        const uint32_t bbase = abase + 16384;
#pragma unroll
        for (int ks = 0; ks < 4; ks++) {
            uint32_t a[2][4];
#pragma unroll
            for (int mt = 0; mt < 2; mt++) {
                uint32_t off = (uint32_t)(wm * 32 + mt * 16 + arow) * 128 + ks * 32 + acol;
                ldm_x4(a[mt], abase + sw128(off));
            }
            uint32_t bf[4][4];
#pragma unroll
            for (int nb2 = 0; nb2 < 4; nb2++) {
                uint32_t off = (uint32_t)(wn * 64 + nb2 * 16 + brow) * 128 + ks * 32 + bcol;
                ldm_x4(bf[nb2], bbase + sw128(off));
            }
#pragma unroll
            for (int mt = 0; mt < 2; mt++)
#pragma unroll
                for (int nb2 = 0; nb2 < 4; nb2++) {
                    mma_16816(acc[mt][nb2 * 2 + 0], a[mt], bf[nb2][0], bf[nb2][1]);
                    mma_16816(acc[mt][nb2 * 2 + 1], a[mt], bf[nb2][2], bf[nb2][3]);
                }
        }
    }

    float* Db = D + (size_t)b * MTOT * NTOT;
    const int mrow = m0 + wm * 32 + (lid >> 2);
    const int ncol = n0 + wn * 64 + (lid & 3) * 2;
#pragma unroll
    for (int mt = 0; mt < 2; mt++)
#pragma unroll
        for (int nb = 0; nb < 8; nb++) {
            const int r0 = mrow + mt * 16;
            const int cc = ncol + nb * 8;
            *reinterpret_cast<float2*>(Db + (size_t)r0 * NTOT + cc) =
                make_float2(acc[mt][nb][0], acc[mt][nb][1]);
            *reinterpret_cast<float2*>(Db + (size_t)(r0 + 8) * NTOT + cc) =
                make_float2(acc[mt][nb][2], acc[mt][nb][3]);
        }
}

// ======================= prep: bf16 hi/lo split =======================
__global__ __launch_bounds__(256)
void split_kernel(const float* __restrict__ X, __nv_bfloat16* __restrict__ Hi,
                  __nv_bfloat16* __restrict__ Lo, size_t n2)
{
    const float2* X2 = reinterpret_cast<const float2*>(X);
    __nv_bfloat162* H2 = reinterpret_cast<__nv_bfloat162*>(Hi);
    __nv_bfloat162* L2 = reinterpret_cast<__nv_bfloat162*>(Lo);
    for (size_t i = (size_t)blockIdx.x * blockDim.x + threadIdx.x; i < n2;
         i += (size_t)gridDim.x * blockDim.x) {
        float2 x = X2[i];
        __nv_bfloat16 h0 = __float2bfloat16(x.x);
        __nv_bfloat16 h1 = __float2bfloat16(x.y);
        H2[i] = __nv_bfloat162(h0, h1);
        L2[i] = __nv_bfloat162(__float2bfloat16(x.x - __bfloat162float(h0)),
                               __float2bfloat16(x.y - __bfloat162float(h1)));
    }
}

// ======== softmax over q (contiguous rows of 512) + sparse compaction ======
// Keeps entries with alpha >= ATHRESH; dropped mass <= 512*ATHRESH ~ 5e-5.
// Ballot-compacted (alpha, q) pairs -> g_list[row][...], count -> g_cnt[row].
static constexpr float ATHRESH = 1e-7f;

__global__ __launch_bounds__(256)
void softmax_compact_kernel(const float* __restrict__ S, Pair* __restrict__ list,
                            int* __restrict__ cnt)
{
    const int row  = blockIdx.x * 8 + (threadIdx.x >> 5);
    const int lane = threadIdx.x & 31;
    const float2* p2 = reinterpret_cast<const float2*>(S + (size_t)row * LQ);

    float2 v[8];
    float mx = -INFINITY;
#pragma unroll
    for (int i = 0; i < 8; i++) {
        v[i] = p2[lane + i * 32];
        mx = fmaxf(mx, fmaxf(v[i].x, v[i].y));
    }
#pragma unroll
    for (int o = 16; o > 0; o >>= 1) mx = fmaxf(mx, __shfl_xor_sync(0xffffffffu, mx, o));
    float sum = 0.f;
#pragma unroll
    for (int i = 0; i < 8; i++) {
        v[i].x = expf(v[i].x - mx);
        v[i].y = expf(v[i].y - mx);
        sum += v[i].x + v[i].y;
    }
#pragma unroll
    for (int o = 16; o > 0; o >>= 1) sum += __shfl_xor_sync(0xffffffffu, sum, o);
    const float inv = 1.f / sum;

    Pair* lrow = list + (size_t)row * LQ;
    const uint32_t ltmask = (1u << lane) - 1u;
    int base = 0;
#pragma unroll
    for (int i = 0; i < 8; i++) {
        // element pair (2q, 2q+1) for q-index lane + i*32 doubled
        float w0 = v[i].x * inv;
        float w1 = v[i].y * inv;
        {
            bool keep = (w0 >= ATHRESH);
            uint32_t m = __ballot_sync(0xffffffffu, keep);
            if (keep) {
                int pos = base + __popc(m & ltmask);
                lrow[pos].a = w0;
                lrow[pos].q = (lane + i * 32) * 2;
            }
            base += __popc(m);
        }
        {
            bool keep = (w1 >= ATHRESH);
            uint32_t m = __ballot_sync(0xffffffffu, keep);
            if (keep) {
                int pos = base + __popc(m & ltmask);
                lrow[pos].a = w1;
                lrow[pos].q = (lane + i * 32) * 2 + 1;
            }
            base += __popc(m);
        }
    }
    if (lane == 0) cnt[row] = base;
}

// ======== sparse gather: out[c,d] = ctx[c,d] * sum_i alpha_i * Q[q_i,d] ====
// One block per (b,c) row; 192 threads x float4 = 768 dims. Q is L2-resident.
__global__ __launch_bounds__(192)
void awq_gather_kernel(const Pair* __restrict__ list, const int* __restrict__ cnt,
                       const float* __restrict__ Q, const float* __restrict__ Ctx,
                       float* __restrict__ Out)
{
    __shared__ Pair sl[LQ];
    const int row = blockIdx.x;          // b*LC + c
    const int b   = row >> 11;           // /LC
    const int t   = threadIdx.x;         // 0..191

    const int n = cnt[row];
    const Pair* lrow = list + (size_t)row * LQ;
    for (int i = t; i < n; i += 192) sl[i] = lrow[i];
    __syncthreads();

    const float4* Q4 = reinterpret_cast<const float4*>(Q + (size_t)b * LQ * DIM);
    float4 acc = make_float4(0.f, 0.f, 0.f, 0.f);
    for (int i = 0; i < n; i++) {
        const float a = sl[i].a;
        const float4 qv = Q4[(size_t)sl[i].q * 192 + t];
        acc.x += a * qv.x;
        acc.y += a * qv.y;
        acc.z += a * qv.z;
        acc.w += a * qv.w;
    }

    const size_t o = (size_t)row * 192 + t;
    const float4 g = reinterpret_cast<const float4*>(Ctx)[o];
    reinterpret_cast<float4*>(Out)[o] =
        make_float4(acc.x * g.x, acc.y * g.y, acc.z * g.z, acc.w * g.w);
}

// tiny marker kernel placed BEFORE gemm1 so ncu's captured launch (sequence
// position 4) lands on the GEMM next profiling run
__global__ void dummy_mark_kernel(float* p) {
    if (threadIdx.x == 0) p[0] = 0.f;
}

// ======================= launch =======================
extern "C" void kernel_launch(void* const* d_in, const int* in_sizes, int n_in,
                              void* d_out, int out_size)
{
    const int ctx_elems = (int)CE;
    const float* ctx, * qry;
    if (in_sizes[0] == ctx_elems) { ctx = (const float*)d_in[0]; qry = (const float*)d_in[1]; }
    else                          { ctx = (const float*)d_in[1]; qry = (const float*)d_in[0]; }
    float* out = (float*)d_out;

    unsigned char* sc = nullptr;
    cudaGetSymbolAddress((void**)&sc, g_scratch);
    float*         S    = (float*)(sc + OFF_S);
    __nv_bfloat16* Chi  = (__nv_bfloat16*)(sc + OFF_CHI);
    __nv_bfloat16* Clo  = (__nv_bfloat16*)(sc + OFF_CLO);
    __nv_bfloat16* Qhi  = (__nv_bfloat16*)(sc + OFF_QHI);
    __nv_bfloat16* Qlo  = (__nv_bfloat16*)(sc + OFF_QLO);
    Pair*          list = (Pair*)(sc + OFF_LIST);
    int*           cnt  = (int*)(sc + OFF_CNT);
    float*         pad  = (float*)(sc + OFF_PAD);

    cudaFuncSetAttribute(mm_hmma_kernel<DIM, LQ, LC>,
                         cudaFuncAttributeMaxDynamicSharedMemorySize, SMEM_DYN_BYTES);

    // 1) split context into bf16 hi/lo
    split_kernel<<<1776, 256>>>(ctx, Chi, Clo, CE / 2);
    // 2) split query into bf16 hi/lo (K-major, as stored)
    split_kernel<<<888, 256>>>(qry, Qhi, Qlo, QE / 2);
    // 3) ncu position marker (GEMM1 lands at captured sequence slot 4)
    dummy_mark_kernel<<<1, 32>>>(pad);
    // 4) GEMM1 (bf16 3-product): S[c,q] = C·Q^T
    {
        dim3 grid(LC / 128, LQ / 128, BATCH);
        mm_hmma_kernel<DIM, LQ, LC><<<grid, 256, SMEM_DYN_BYTES>>>(
            Chi, Clo, Chi, Qhi, Qhi, Qlo, S);
    }
    // 5) softmax over q + sparse (alpha, q) compaction
    softmax_compact_kernel<<<NROWS / 8, 256>>>(S, list, cnt);
    // 6) sparse gather + gate: out[c,d] = ctx[c,d] * sum_i alpha_i Q[q_i,d]
    awq_gather_kernel<<<NROWS, 192>>>(list, cnt, qry, ctx, out);
    (void)n_in; (void)out_size;
}